// round 8
// baseline (speedup 1.0000x reference)
#include <cuda_runtime.h>
#include <math.h>

#define BB 4
#define NN 2048
#define CC 256
#define HH 8
#define LL 2
#define RAD2 0.09f
#define EPSV 1e-5f
#define NROWS (BB*NN)
#define EG 64
#define KG 33
#define GROWS (EG*KG)

__device__ float g_x [NROWS*CC];
__device__ float g_q [NROWS*CC];
__device__ float g_k [NROWS*CC];
__device__ float g_v [NROWS*CC];
__device__ float g_ao[NROWS*CC];
__device__ float g_pr[NROWS*CC];
__device__ float g_z1[NROWS*64];
__device__ float g_z2[NROWS*32];
__device__ float g_z3[NROWS*16];
__device__ float g_mu1[64],  g_var1[64];
__device__ float g_mu2[32],  g_var2[32];
__device__ float g_mu3[16],  g_var3[16];
__device__ int   g_idx[EG];
__device__ float g_grouped[GROWS*3];
__device__ float g_zg1[GROWS*64];
__device__ float g_zg2[GROWS*256];
__device__ float g_zg3[GROWS*512];
__device__ float g_mug1[64],  g_varg1[64];
__device__ float g_mug2[256], g_varg2[256];
__device__ float g_mug3[512], g_varg3[512];

// ---------------- bf16 double-double helpers ----------------
__device__ __forceinline__ unsigned bfpack(float lo, float hi) {
    unsigned r;
    asm("cvt.rn.bf16x2.f32 %0, %1, %2;" : "=r"(r) : "f"(hi), "f"(lo));
    return r;
}
__device__ __forceinline__ uint2 bfsplit2(float x0, float x1) {
    unsigned hp = bfpack(x0, x1);
    float h0 = __uint_as_float(hp << 16);
    float h1 = __uint_as_float(hp & 0xffff0000u);
    unsigned lp = bfpack(x0 - h0, x1 - h1);
    return make_uint2(hp, lp);
}
__device__ __forceinline__ void mmabf(float* d,
                                      unsigned a0, unsigned a1, unsigned a2, unsigned a3,
                                      unsigned b0, unsigned b1) {
    asm volatile("mma.sync.aligned.m16n8k16.row.col.f32.bf16.bf16.f32 "
        "{%0,%1,%2,%3}, {%4,%5,%6,%7}, {%8,%9}, {%0,%1,%2,%3};"
        : "+f"(d[0]), "+f"(d[1]), "+f"(d[2]), "+f"(d[3])
        : "r"(a0), "r"(a1), "r"(a2), "r"(a3), "r"(b0), "r"(b1));
}
__device__ __forceinline__ void mma3(float* d, const uint2* a, uint2 b0, uint2 b1) {
    mmabf(d, a[0].x, a[1].x, a[2].x, a[3].x, b0.x, b1.x);
    mmabf(d, a[0].x, a[1].x, a[2].x, a[3].x, b0.y, b1.y);
    mmabf(d, a[0].y, a[1].y, a[2].y, a[3].y, b0.x, b1.x);
}

// ---------------- tf32 helpers (k_gemm_bt) ----------------
__device__ __forceinline__ uint2 tf32x2(float x) {
    unsigned hi, lo;
    asm("cvt.rna.tf32.f32 %0, %1;" : "=r"(hi) : "f"(x));
    float r = x - __uint_as_float(hi);
    asm("cvt.rna.tf32.f32 %0, %1;" : "=r"(lo) : "f"(r));
    return make_uint2(hi, lo);
}
__device__ __forceinline__ void mma8(float* d,
                                     unsigned a0, unsigned a1, unsigned a2, unsigned a3,
                                     unsigned b0, unsigned b1) {
    asm volatile("mma.sync.aligned.m16n8k8.row.col.f32.tf32.tf32.f32 "
        "{%0,%1,%2,%3}, {%4,%5,%6,%7}, {%8,%9}, {%0,%1,%2,%3};"
        : "+f"(d[0]), "+f"(d[1]), "+f"(d[2]), "+f"(d[3])
        : "r"(a0), "r"(a1), "r"(a2), "r"(a3), "r"(b0), "r"(b1));
}
__device__ __forceinline__ void mma_x3t(float* d, const uint2* a, uint2 b0, uint2 b1) {
    mma8(d, a[0].x, a[1].x, a[2].x, a[3].x, b0.x, b1.x);
    mma8(d, a[0].x, a[1].x, a[2].x, a[3].x, b0.y, b1.y);
    mma8(d, a[0].y, a[1].y, a[2].y, a[3].y, b0.x, b1.x);
}

// ---------------- (B,C,N) -> (B,N,C) ----------------
__global__ __launch_bounds__(256) void k_transpose(const float* __restrict__ src,
                                                   float* __restrict__ dst) {
    __shared__ float t[32][33];
    int b = blockIdx.z, n0 = blockIdx.x*32, c0 = blockIdx.y*32;
    int tx = threadIdx.x, ty = threadIdx.y;
    #pragma unroll
    for (int i = 0; i < 32; i += 8)
        t[ty+i][tx] = src[((size_t)b*CC + c0 + ty + i)*NN + n0 + tx];
    __syncthreads();
    #pragma unroll
    for (int i = 0; i < 32; i += 8)
        dst[((size_t)b*NN + n0 + ty + i)*CC + c0 + tx] = t[tx][ty+i];
}

// ---------------- bf16x3 GEMM, prefetch-pipelined, 3 B/C via blockIdx.z -----
#define AS_RS 20
#define BT_RS 20
__global__ __launch_bounds__(256) void k_gemm3(const float* __restrict__ A,
                                               const float* __restrict__ B0,
                                               const float* __restrict__ B1,
                                               const float* __restrict__ B2,
                                               float* __restrict__ C0,
                                               float* __restrict__ C1,
                                               float* __restrict__ C2,
                                               int Kd, int Nc) {
    __shared__ uint2 As[128*AS_RS];
    __shared__ uint2 Bt[64*BT_RS];
    const float* B = (blockIdx.z == 0) ? B0 : (blockIdx.z == 1 ? B1 : B2);
    float*       C = (blockIdx.z == 0) ? C0 : (blockIdx.z == 1 ? C1 : C2);
    int tid = threadIdx.x;
    int w = tid >> 5, lane = tid & 31, g = lane >> 2, tg = lane & 3;
    int mt = w >> 1, nh = w & 1;
    int bm = blockIdx.x*128, bn = blockIdx.y*64;
    float acc[2][4][4];
    #pragma unroll
    for (int m = 0; m < 2; m++)
        #pragma unroll
        for (int nt = 0; nt < 4; nt++)
            #pragma unroll
            for (int i = 0; i < 4; i++) acc[m][nt][i] = 0.f;

    int bkp = tid & 15, bng = tid >> 4;
    int ar = tid >> 1, ac = (tid & 1) << 4;   // A: 128 rows x 2 threads, 16 cols each

    float4 apf[4];        // A prefetch: 16 consecutive cols of one row
    float4 bpx, bpy;      // B prefetch

    // prefetch k0 = 0
    {
        const float* ap = A + (size_t)(bm+ar)*Kd + ac;
        apf[0] = *(const float4*)(ap + 0);
        apf[1] = *(const float4*)(ap + 4);
        apf[2] = *(const float4*)(ap + 8);
        apf[3] = *(const float4*)(ap + 12);
        const float* bp0 = B + (size_t)(2*bkp)*Nc + bn + 4*bng;
        bpx = *(const float4*)bp0;
        bpy = *(const float4*)(bp0 + Nc);
    }

    for (int k0 = 0; k0 < Kd; k0 += 32) {
        // convert + store staged registers
        #pragma unroll
        for (int it = 0; it < 4; it++) {
            float4 v = apf[it];
            uint2 p0 = bfsplit2(v.x, v.y), p1 = bfsplit2(v.z, v.w);
            *(uint4*)&As[ar*AS_RS + ((ac + 4*it) >> 1)] = make_uint4(p0.x, p0.y, p1.x, p1.y);
        }
        Bt[(4*bng+0)*BT_RS + bkp] = bfsplit2(bpx.x, bpy.x);
        Bt[(4*bng+1)*BT_RS + bkp] = bfsplit2(bpx.y, bpy.y);
        Bt[(4*bng+2)*BT_RS + bkp] = bfsplit2(bpx.z, bpy.z);
        Bt[(4*bng+3)*BT_RS + bkp] = bfsplit2(bpx.w, bpy.w);
        __syncthreads();

        // issue next chunk's loads (overlap with compute)
        if (k0 + 32 < Kd) {
            const float* ap = A + (size_t)(bm+ar)*Kd + k0 + 32 + ac;
            apf[0] = *(const float4*)(ap + 0);
            apf[1] = *(const float4*)(ap + 4);
            apf[2] = *(const float4*)(ap + 8);
            apf[3] = *(const float4*)(ap + 12);
            const float* bp0 = B + (size_t)(k0 + 32 + 2*bkp)*Nc + bn + 4*bng;
            bpx = *(const float4*)bp0;
            bpy = *(const float4*)(bp0 + Nc);
        }

        #pragma unroll
        for (int kk = 0; kk < 2; kk++) {
            int kb = kk*8;
            uint2 af[2][4];
            #pragma unroll
            for (int m = 0; m < 2; m++) {
                int r0 = mt*32 + m*16 + g;
                af[m][0] = As[r0*AS_RS + kb+tg];
                af[m][1] = As[(r0+8)*AS_RS + kb+tg];
                af[m][2] = As[r0*AS_RS + kb+tg+4];
                af[m][3] = As[(r0+8)*AS_RS + kb+tg+4];
            }
            #pragma unroll
            for (int nt = 0; nt < 4; nt++) {
                int n0 = nh*32 + nt*8;
                uint2 b0 = Bt[(n0+g)*BT_RS + kb+tg];
                uint2 b1 = Bt[(n0+g)*BT_RS + kb+tg+4];
                mma3(acc[0][nt], af[0], b0, b1);
                mma3(acc[1][nt], af[1], b0, b1);
            }
        }
        __syncthreads();
    }
    #pragma unroll
    for (int m = 0; m < 2; m++)
        #pragma unroll
        for (int nt = 0; nt < 4; nt++) {
            int row = bm + mt*32 + m*16 + g;
            int col = bn + nh*32 + nt*8 + 2*tg;
            *(float2*)(C + (size_t)row*Nc + col) = make_float2(acc[m][nt][0], acc[m][nt][1]);
            *(float2*)(C + (size_t)(row+8)*Nc + col) = make_float2(acc[m][nt][2], acc[m][nt][3]);
        }
}

// ------- tf32x3 GEMM, B transposed (W[N x K] row-major), optional BN+act ----
__global__ __launch_bounds__(256) void k_gemm_bt(const float* __restrict__ A,
                                                 const float* __restrict__ W,
                                                 const float* __restrict__ bias,
                                                 const float* __restrict__ mu,
                                                 const float* __restrict__ var,
                                                 const float* __restrict__ gam,
                                                 const float* __restrict__ bet,
                                                 int act,
                                                 float* __restrict__ C,
                                                 int M, int Kd, int Nc) {
    __shared__ float As[128][36];
    __shared__ float Ws[64][36];
    int tid = threadIdx.x;
    int w = tid >> 5, lane = tid & 31, g = lane >> 2, tg = lane & 3;
    int mt = w >> 1, nh = w & 1;
    int bm = blockIdx.x*128, bn = blockIdx.y*64;
    float acc[2][4][4];
    #pragma unroll
    for (int m = 0; m < 2; m++)
        #pragma unroll
        for (int nt = 0; nt < 4; nt++)
            #pragma unroll
            for (int i = 0; i < 4; i++) acc[m][nt][i] = 0.f;

    for (int k0 = 0; k0 < Kd; k0 += 32) {
        #pragma unroll
        for (int it = 0; it < 4; it++) {
            int i = tid + it*256;
            int r = i >> 3, c = (i & 7) << 2;
            int gr = bm + r;
            float4 v = (gr < M) ? *(const float4*)(A + (size_t)gr*Kd + k0 + c)
                                : make_float4(0.f,0.f,0.f,0.f);
            if (act == 2) {
                float* vv = (float*)&v;
                #pragma unroll
                for (int j = 0; j < 4; j++) {
                    int cc = k0 + c + j;
                    float sc = gam[cc]*rsqrtf(var[cc]+EPSV);
                    float t = (vv[j] - mu[cc])*sc + bet[cc];
                    vv[j] = (t > 0.f) ? t : 0.2f*t;
                }
            }
            *(float4*)&As[r][c] = v;
        }
        #pragma unroll
        for (int it = 0; it < 2; it++) {
            int i = tid + it*256;
            int r = i >> 3, c = (i & 7) << 2;
            *(float4*)&Ws[r][c] = *(const float4*)(W + (size_t)(bn+r)*Kd + k0 + c);
        }
        __syncthreads();
        #pragma unroll
        for (int kk = 0; kk < 4; kk++) {
            int kb = kk*8;
            uint2 af[2][4];
            #pragma unroll
            for (int m = 0; m < 2; m++) {
                int r0 = mt*32 + m*16 + g;
                af[m][0] = tf32x2(As[r0  ][kb+tg]);
                af[m][1] = tf32x2(As[r0+8][kb+tg]);
                af[m][2] = tf32x2(As[r0  ][kb+tg+4]);
                af[m][3] = tf32x2(As[r0+8][kb+tg+4]);
            }
            #pragma unroll
            for (int nt = 0; nt < 4; nt++) {
                int n0 = nh*32 + nt*8;
                uint2 b0 = tf32x2(Ws[n0+g][kb+tg]);
                uint2 b1 = tf32x2(Ws[n0+g][kb+tg+4]);
                mma_x3t(acc[0][nt], af[0], b0, b1);
                mma_x3t(acc[1][nt], af[1], b0, b1);
            }
        }
        __syncthreads();
    }
    #pragma unroll
    for (int m = 0; m < 2; m++)
        #pragma unroll
        for (int nt = 0; nt < 4; nt++) {
            int row = bm + mt*32 + m*16 + g;
            int col = bn + nh*32 + nt*8 + 2*tg;
            float b0v = bias ? bias[col]   : 0.f;
            float b1v = bias ? bias[col+1] : 0.f;
            if (row < M)
                *(float2*)(C + (size_t)row*Nc + col) =
                    make_float2(acc[m][nt][0]+b0v, acc[m][nt][1]+b1v);
            if (row + 8 < M)
                *(float2*)(C + (size_t)(row+8)*Nc + col) =
                    make_float2(acc[m][nt][2]+b0v, acc[m][nt][3]+b1v);
        }
}

// -------- flash attention: prefetch-pipelined staging, register softmax ----
#define KS_RS 20
#define VT_RS 36
__global__ __launch_bounds__(256) void k_flash(const float* __restrict__ Q,
                                               const float* __restrict__ K,
                                               const float* __restrict__ V,
                                               float* __restrict__ O) {
    __shared__ uint2 Ks[64*KS_RS];
    __shared__ uint2 Vt[32*VT_RS];

    int tid = threadIdx.x;
    int w = tid >> 5, lane = tid & 31, g = lane >> 2, tg = lane & 3;
    int qt = blockIdx.x, h = blockIdx.y, b = blockIdx.z;
    const size_t rowbase = (size_t)b*NN + (size_t)qt*128;
    const float* qb = Q + rowbase*CC + h*32;
    const float* kb = K + (size_t)b*NN*CC + h*32;
    const float* vb = V + (size_t)b*NN*CC + h*32;

    const float qsc = 0.1767766952966369f * 1.4426950408889634f;
    int r0 = w*16 + g;
    uint2 qf[2][4];
    #pragma unroll
    for (int kk = 0; kk < 2; kk++) {
        int cb = kk*16 + 2*tg;
        float2 x0 = *(const float2*)(qb + (size_t)r0*CC + cb);
        float2 x1 = *(const float2*)(qb + (size_t)(r0+8)*CC + cb);
        float2 x2 = *(const float2*)(qb + (size_t)r0*CC + cb + 8);
        float2 x3 = *(const float2*)(qb + (size_t)(r0+8)*CC + cb + 8);
        qf[kk][0] = bfsplit2(x0.x*qsc, x0.y*qsc);
        qf[kk][1] = bfsplit2(x1.x*qsc, x1.y*qsc);
        qf[kk][2] = bfsplit2(x2.x*qsc, x2.y*qsc);
        qf[kk][3] = bfsplit2(x3.x*qsc, x3.y*qsc);
    }

    float of[4][4];
    #pragma unroll
    for (int nt = 0; nt < 4; nt++)
        #pragma unroll
        for (int i = 0; i < 4; i++) of[nt][i] = 0.f;
    float l0 = 0.f, l1 = 0.f;

    // staging tasks
    int kr0 = tid >> 3, kc0 = (tid & 7) << 2;  // K: rows kr0 and kr0+32
    int vj = tid & 31, vcq = tid >> 5;         // V: key pair 2vj, dh cols vcq*4

    float4 kpf0, kpf1, vpf0, vpf1;
    {   // prefetch chunk 0
        kpf0 = *(const float4*)(kb + (size_t)kr0*CC + kc0);
        kpf1 = *(const float4*)(kb + (size_t)(kr0+32)*CC + kc0);
        const float* v0 = vb + (size_t)(2*vj)*CC + vcq*4;
        vpf0 = *(const float4*)v0;
        vpf1 = *(const float4*)(v0 + CC);
    }

    for (int c0 = 0; c0 < NN; c0 += 64) {
        // convert + store staged registers
        {
            uint2 p0 = bfsplit2(kpf0.x, kpf0.y), p1 = bfsplit2(kpf0.z, kpf0.w);
            *(uint4*)&Ks[kr0*KS_RS + (kc0 >> 1)] = make_uint4(p0.x, p0.y, p1.x, p1.y);
            p0 = bfsplit2(kpf1.x, kpf1.y); p1 = bfsplit2(kpf1.z, kpf1.w);
            *(uint4*)&Ks[(kr0+32)*KS_RS + (kc0 >> 1)] = make_uint4(p0.x, p0.y, p1.x, p1.y);
            int c = vcq*4;
            Vt[(c+0)*VT_RS + vj] = bfsplit2(vpf0.x, vpf1.x);
            Vt[(c+1)*VT_RS + vj] = bfsplit2(vpf0.y, vpf1.y);
            Vt[(c+2)*VT_RS + vj] = bfsplit2(vpf0.z, vpf1.z);
            Vt[(c+3)*VT_RS + vj] = bfsplit2(vpf0.w, vpf1.w);
        }
        __syncthreads();

        // issue next chunk's loads (overlap with compute)
        if (c0 + 64 < NN) {
            int cn = c0 + 64;
            kpf0 = *(const float4*)(kb + (size_t)(cn+kr0)*CC + kc0);
            kpf1 = *(const float4*)(kb + (size_t)(cn+kr0+32)*CC + kc0);
            const float* v0 = vb + (size_t)(cn + 2*vj)*CC + vcq*4;
            vpf0 = *(const float4*)v0;
            vpf1 = *(const float4*)(v0 + CC);
        }

        // S (log2 domain) -> exp2 -> bf16 pairs in registers
        uint2 Pl[8], Ph[8];
        #pragma unroll
        for (int nt = 0; nt < 8; nt++) {
            float sacc[4] = {0.f, 0.f, 0.f, 0.f};
            int n0 = nt*8;
            #pragma unroll
            for (int kk = 0; kk < 2; kk++) {
                int kb2 = kk*8;
                uint2 b0 = Ks[(n0+g)*KS_RS + kb2+tg];
                uint2 b1 = Ks[(n0+g)*KS_RS + kb2+tg+4];
                mma3(sacc, qf[kk], b0, b1);
            }
            float e0 = exp2f(sacc[0]), e1 = exp2f(sacc[1]);
            float e2 = exp2f(sacc[2]), e3 = exp2f(sacc[3]);
            l0 += e0 + e1;
            l1 += e2 + e3;
            Pl[nt] = bfsplit2(e0, e1);
            Ph[nt] = bfsplit2(e2, e3);
        }
        // O += P @ V
        #pragma unroll
        for (int kk = 0; kk < 4; kk++) {
            uint2 pa[4] = {Pl[2*kk], Ph[2*kk], Pl[2*kk+1], Ph[2*kk+1]};
            int kb2 = kk*8;
            #pragma unroll
            for (int nt = 0; nt < 4; nt++) {
                int n0 = nt*8;
                uint2 b0 = Vt[(n0+g)*VT_RS + kb2+tg];
                uint2 b1 = Vt[(n0+g)*VT_RS + kb2+tg+4];
                mma3(of[nt], pa, b0, b1);
            }
        }
        __syncthreads();
    }

    l0 += __shfl_xor_sync(0xffffffffu, l0, 1);
    l0 += __shfl_xor_sync(0xffffffffu, l0, 2);
    l1 += __shfl_xor_sync(0xffffffffu, l1, 1);
    l1 += __shfl_xor_sync(0xffffffffu, l1, 2);
    float inv0 = 1.f / l0, inv1 = 1.f / l1;
    #pragma unroll
    for (int nt = 0; nt < 4; nt++) {
        int c = nt*8 + 2*tg;
        *(float2*)(O + (rowbase + r0)*CC + h*32 + c) =
            make_float2(of[nt][0]*inv0, of[nt][1]*inv0);
        *(float2*)(O + (rowbase + r0 + 8)*CC + h*32 + c) =
            make_float2(of[nt][2]*inv1, of[nt][3]*inv1);
    }
}

__global__ __launch_bounds__(256) void k_lnres(const float* __restrict__ xin,
                                               const float* __restrict__ o,
                                               const float* __restrict__ g,
                                               const float* __restrict__ bta,
                                               float* __restrict__ xout) {
    int row = blockIdx.x*8 + threadIdx.y;
    int lane = threadIdx.x;
    const float* xr = xin + (size_t)row*CC;
    const float* orr = o + (size_t)row*CC;
    float v[8]; float s = 0.f;
    #pragma unroll
    for (int i = 0; i < 8; i++) { int c = lane + i*32; v[i] = xr[c] + orr[c]; s += v[i]; }
    #pragma unroll
    for (int off = 16; off; off >>= 1) s += __shfl_xor_sync(0xffffffffu, s, off);
    float mean = s * (1.f/256.f);
    float vs = 0.f;
    #pragma unroll
    for (int i = 0; i < 8; i++) { float d = v[i]-mean; vs += d*d; }
    #pragma unroll
    for (int off = 16; off; off >>= 1) vs += __shfl_xor_sync(0xffffffffu, vs, off);
    float rstd = rsqrtf(vs*(1.f/256.f) + EPSV);
    #pragma unroll
    for (int i = 0; i < 8; i++) {
        int c = lane + i*32;
        xout[(size_t)row*CC + c] = (v[i]-mean)*rstd*g[c] + bta[c];
    }
}

__global__ __launch_bounds__(256) void k_stats(const float* __restrict__ z, int rows, int C,
                                               float* __restrict__ mu, float* __restrict__ var) {
    int lane = threadIdx.x & 31;
    int rl = threadIdx.x >> 5;
    int c = blockIdx.x*32 + lane;
    float s = 0.f, sq = 0.f;
    if (c < C)
        for (int r = rl; r < rows; r += 8) {
            float v = z[(size_t)r*C + c]; s += v; sq += v*v;
        }
    __shared__ float ss[8][33], qq[8][33];
    ss[rl][lane] = s; qq[rl][lane] = sq;
    __syncthreads();
    if (rl == 0 && c < C) {
        float S = 0.f, Qq = 0.f;
        #pragma unroll
        for (int j = 0; j < 8; j++) { S += ss[j][lane]; Qq += qq[j][lane]; }
        float m = S / rows;
        mu[c] = m; var[c] = fmaxf(Qq / rows - m*m, 0.f);
    }
}

__global__ __launch_bounds__(256) void k_dense(const float* __restrict__ in, int Cin,
                                               const float* __restrict__ w,
                                               const float* __restrict__ bias,
                                               const float* __restrict__ mu,
                                               const float* __restrict__ var,
                                               const float* __restrict__ gam,
                                               const float* __restrict__ bet,
                                               int act,
                                               float* __restrict__ out, int Cout) {
    __shared__ float a_s[32*64];
    int rowbase = blockIdx.x*32;
    int tid = threadIdx.x;
    for (int i = tid; i < 32*Cin; i += 256) {
        int r = i / Cin, c = i - r*Cin;
        float v = in[(size_t)(rowbase+r)*Cin + c];
        if (act) {
            float sc = gam[c]*rsqrtf(var[c]+EPSV);
            v = (v - mu[c])*sc + bet[c];
            v = (act == 1) ? fmaxf(v, 0.f) : (v > 0.f ? v : 0.2f*v);
        }
        a_s[i] = v;
    }
    __syncthreads();
    int npairs = Cout*4;
    for (int pr = tid; pr < npairs; pr += 256) {
        int o = pr % Cout, rb = (pr / Cout)*8;
        float bz = bias ? bias[o] : 0.f;
        float acc[8];
        #pragma unroll
        for (int r = 0; r < 8; r++) acc[r] = bz;
        const float* wr = w + (size_t)o*Cin;
        for (int c = 0; c < Cin; c += 4) {
            float4 wv = *(const float4*)(wr + c);
            #pragma unroll
            for (int r = 0; r < 8; r++) {
                float4 av = *(const float4*)(a_s + (rb+r)*Cin + c);
                acc[r] += wv.x*av.x + wv.y*av.y + wv.z*av.z + wv.w*av.w;
            }
        }
        #pragma unroll
        for (int r = 0; r < 8; r++)
            out[(size_t)(rowbase+rb+r)*Cout + o] = acc[r];
    }
}

__global__ __launch_bounds__(256) void k_argmax(const float* __restrict__ z3,
                                                const float* __restrict__ mu,
                                                const float* __restrict__ var,
                                                const float* __restrict__ gam,
                                                const float* __restrict__ bet,
                                                int* __restrict__ idx) {
    int bc = blockIdx.x;
    int b = bc >> 4, c = bc & 15;
    int tid = threadIdx.x;
    float sc = gam[c]*rsqrtf(var[c]+EPSV);
    float sh = bet[c] - mu[c]*sc;
    float best = -1.f; int bi = 1 << 30;
    for (int n = tid; n < NN; n += 256) {
        float v = fmaxf(z3[(size_t)(b*NN+n)*16 + c]*sc + sh, 0.f);
        if (v > best) { best = v; bi = n; }
    }
    __shared__ float bv[256]; __shared__ int bx[256];
    bv[tid] = best; bx[tid] = bi;
    __syncthreads();
    for (int off = 128; off; off >>= 1) {
        if (tid < off) {
            if (bv[tid+off] > bv[tid] || (bv[tid+off] == bv[tid] && bx[tid+off] < bx[tid])) {
                bv[tid] = bv[tid+off]; bx[tid] = bx[tid+off];
            }
        }
        __syncthreads();
    }
    if (tid == 0) idx[bc] = bx[0];
}

__global__ void k_ballq(const float* __restrict__ pts, const int* __restrict__ idx,
                        float* __restrict__ grouped) {
    int e = blockIdx.x;
    int b = e >> 4;
    int lane = threadIdx.x;
    const float* px = pts + (size_t)b*3*NN;
    int qi = idx[e];
    float qx = px[qi], qy = px[NN+qi], qz = px[2*NN+qi];
    float qq = qx*qx + qy*qy + qz*qz;
    __shared__ int gi[32];
    int cnt = 0;
    for (int base = 0; base < NN && cnt < 32; base += 32) {
        int n = base + lane;
        float x = px[n], y = px[NN+n], z = px[2*NN+n];
        float pp = x*x + y*y + z*z;
        float d = qq + pp - 2.f*(qx*x + qy*y + qz*z);
        bool in = !(d > RAD2);
        unsigned m = __ballot_sync(0xffffffffu, in);
        int pos = cnt + __popc(m & ((1u << lane) - 1u));
        if (in && pos < 32) gi[pos] = n;
        cnt += __popc(m);
    }
    __syncwarp();
    if (cnt > 32) cnt = 32;
    int g0 = gi[0];
    int g = (lane < cnt) ? gi[lane] : g0;
    if (lane == 0) {
        grouped[(size_t)e*KG*3+0] = qx;
        grouped[(size_t)e*KG*3+1] = qy;
        grouped[(size_t)e*KG*3+2] = qz;
    }
    size_t o = ((size_t)e*KG + 1 + lane)*3;
    grouped[o+0] = px[g]; grouped[o+1] = px[NN+g]; grouped[o+2] = px[2*NN+g];
}

__global__ __launch_bounds__(256) void k_gc1(const float* __restrict__ grouped,
                                             const float* __restrict__ w,
                                             float* __restrict__ out) {
    int i = blockIdx.x*256 + threadIdx.x;
    if (i >= GROWS*64) return;
    int o = i & 63, r = i >> 6;
    const float* p = grouped + (size_t)r*3;
    const float* wr = w + o*3;
    out[i] = wr[0]*p[0] + wr[1]*p[1] + wr[2]*p[2];
}

__global__ __launch_bounds__(256) void k_finalmax(const float* __restrict__ zg3,
                                                  const float* __restrict__ mu,
                                                  const float* __restrict__ var,
                                                  const float* __restrict__ gam,
                                                  const float* __restrict__ bet,
                                                  float* __restrict__ out) {
    int i = blockIdx.x*256 + threadIdx.x;
    if (i >= EG*512) return;
    int c = i & 511, e = i >> 9;
    int b = e >> 4, s = e & 15;
    float sc = gam[c]*rsqrtf(var[c]+EPSV);
    float sh = bet[c] - mu[c]*sc;
    float mx = -3.0e30f;
    const float* base = zg3 + (size_t)e*KG*512 + c;
    #pragma unroll 1
    for (int k = 0; k < KG; k++) {
        float v = base[(size_t)k*512]*sc + sh;
        v = (v > 0.f) ? v : 0.2f*v;
        mx = fmaxf(mx, v);
    }
    out[((size_t)b*512 + c)*16 + s] = mx;
}

extern "C" void kernel_launch(void* const* d_in, const int* in_sizes, int n_in,
                              void* d_out, int out_size) {
    const float* hoch = (const float*)d_in[0];
    const float* pts  = (const float*)d_in[1];
    const float* Wq   = (const float*)d_in[2];
    const float* Wk   = (const float*)d_in[3];
    const float* Wv   = (const float*)d_in[4];
    const float* Wo   = (const float*)d_in[5];
    const float* ln_g = (const float*)d_in[6];
    const float* ln_b = (const float*)d_in[7];
    const float* fgw1 = (const float*)d_in[8];
    const float* fgb1 = (const float*)d_in[9];
    const float* fgw2 = (const float*)d_in[10];
    const float* fgb2 = (const float*)d_in[11];
    const float* fgw3 = (const float*)d_in[12];
    const float* fgb3 = (const float*)d_in[13];
    const float* fgg1 = (const float*)d_in[14];
    const float* fge1 = (const float*)d_in[15];
    const float* fgg2 = (const float*)d_in[16];
    const float* fge2 = (const float*)d_in[17];
    const float* fgg3 = (const float*)d_in[18];
    const float* fge3 = (const float*)d_in[19];
    const float* cw1  = (const float*)d_in[20];
    const float* cw2  = (const float*)d_in[21];
    const float* cw3  = (const float*)d_in[22];
    const float* cg1  = (const float*)d_in[23];
    const float* cb1  = (const float*)d_in[24];
    const float* cg2  = (const float*)d_in[25];
    const float* cb2  = (const float*)d_in[26];
    const float* cg3  = (const float*)d_in[27];
    const float* cb3  = (const float*)d_in[28];
    float* out = (float*)d_out;

    void* a;
    cudaGetSymbolAddress(&a, g_x);       float* x   = (float*)a;
    cudaGetSymbolAddress(&a, g_q);       float* q   = (float*)a;
    cudaGetSymbolAddress(&a, g_k);       float* k   = (float*)a;
    cudaGetSymbolAddress(&a, g_v);       float* v   = (float*)a;
    cudaGetSymbolAddress(&a, g_ao);      float* ao  = (float*)a;
    cudaGetSymbolAddress(&a, g_pr);      float* pr  = (float*)a;
    cudaGetSymbolAddress(&a, g_z1);      float* z1  = (float*)a;
    cudaGetSymbolAddress(&a, g_z2);      float* z2  = (float*)a;
    cudaGetSymbolAddress(&a, g_z3);      float* z3  = (float*)a;
    cudaGetSymbolAddress(&a, g_mu1);     float* mu1 = (float*)a;
    cudaGetSymbolAddress(&a, g_var1);    float* va1 = (float*)a;
    cudaGetSymbolAddress(&a, g_mu2);     float* mu2 = (float*)a;
    cudaGetSymbolAddress(&a, g_var2);    float* va2 = (float*)a;
    cudaGetSymbolAddress(&a, g_mu3);     float* mu3 = (float*)a;
    cudaGetSymbolAddress(&a, g_var3);    float* va3 = (float*)a;
    cudaGetSymbolAddress(&a, g_idx);     int*   idx = (int*)a;
    cudaGetSymbolAddress(&a, g_grouped); float* grp = (float*)a;
    cudaGetSymbolAddress(&a, g_zg1);     float* zg1 = (float*)a;
    cudaGetSymbolAddress(&a, g_zg2);     float* zg2 = (float*)a;
    cudaGetSymbolAddress(&a, g_zg3);     float* zg3 = (float*)a;
    cudaGetSymbolAddress(&a, g_mug1);    float* mg1 = (float*)a;
    cudaGetSymbolAddress(&a, g_varg1);   float* vg1 = (float*)a;
    cudaGetSymbolAddress(&a, g_mug2);    float* mg2 = (float*)a;
    cudaGetSymbolAddress(&a, g_varg2);   float* vg2 = (float*)a;
    cudaGetSymbolAddress(&a, g_mug3);    float* mg3 = (float*)a;
    cudaGetSymbolAddress(&a, g_varg3);   float* vg3 = (float*)a;

    k_transpose<<<dim3(NN/32, CC/32, BB), dim3(32,8)>>>(hoch, x);

    for (int l = 0; l < LL; l++) {
        const float* wq = Wq + (size_t)l*CC*CC;
        const float* wk = Wk + (size_t)l*CC*CC;
        const float* wv = Wv + (size_t)l*CC*CC;
        const float* wo = Wo + (size_t)l*CC*CC;
        k_gemm3<<<dim3(NROWS/128, CC/64, 3), 256>>>(x, wq, wk, wv, q, k, v, CC, CC);
        k_flash<<<dim3(NN/128, HH, BB), 256>>>(q, k, v, ao);
        k_gemm3<<<dim3(NROWS/128, CC/64, 1), 256>>>(ao, wo, wo, wo, pr, pr, pr, CC, CC);
        k_lnres<<<NROWS/8, dim3(32,8)>>>(x, pr, ln_g + l*CC, ln_b + l*CC, x);
    }

    k_gemm_bt<<<dim3(NROWS/128, 1), 256>>>(x, fgw1, fgb1, 0, 0, 0, 0, 0, z1, NROWS, 256, 64);
    k_stats<<<2, 256>>>(z1, NROWS, 64, mu1, va1);
    k_dense<<<NROWS/32, 256>>>(z1, 64, fgw2, fgb2, mu1, va1, fgg1, fge1, 1, z2, 32);
    k_stats<<<1, 256>>>(z2, NROWS, 32, mu2, va2);
    k_dense<<<NROWS/32, 256>>>(z2, 32, fgw3, fgb3, mu2, va2, fgg2, fge2, 1, z3, 16);
    k_stats<<<1, 256>>>(z3, NROWS, 16, mu3, va3);
    k_argmax<<<EG, 256>>>(z3, mu3, va3, fgg3, fge3, idx);

    k_ballq<<<EG, 32>>>(pts, idx, grp);
    k_gc1<<<(GROWS*64 + 255)/256, 256>>>(grp, cw1, zg1);
    k_stats<<<2, 256>>>(zg1, GROWS, 64, mg1, vg1);
    k_dense<<<GROWS/32, 256>>>(zg1, 64, cw2, 0, mg1, vg1, cg1, cb1, 2, zg2, 256);
    k_stats<<<8, 256>>>(zg2, GROWS, 256, mg2, vg2);
    k_gemm_bt<<<dim3((GROWS+127)/128, 8), 256>>>(zg2, cw3, 0, mg2, vg2, cg2, cb2, 2, zg3, GROWS, 256, 512);
    k_stats<<<16, 256>>>(zg3, GROWS, 512, mg3, vg3);
    k_finalmax<<<(EG*512 + 255)/256, 256>>>(zg3, mg3, vg3, cg3, cb3, out);
}

// round 14
// speedup vs baseline: 1.0508x; 1.0508x over previous
#include <cuda_runtime.h>
#include <math.h>

#define BB 4
#define NN 2048
#define CC 256
#define HH 8
#define LL 2
#define RAD2 0.09f
#define EPSV 1e-5f
#define NROWS (BB*NN)
#define EG 64
#define KG 33
#define GROWS (EG*KG)

__device__ float g_x [NROWS*CC];
__device__ float g_q [NROWS*CC];
__device__ float g_k [NROWS*CC];
__device__ float g_v [NROWS*CC];
__device__ float g_ao[NROWS*CC];
__device__ float g_pr[NROWS*CC];
__device__ float g_z1[NROWS*64];
__device__ float g_z2[NROWS*32];
__device__ float g_z3[NROWS*16];
__device__ float g_mu1[64],  g_var1[64];
__device__ float g_mu2[32],  g_var2[32];
__device__ float g_mu3[16],  g_var3[16];
__device__ int   g_idx[EG];
__device__ float g_grouped[GROWS*3];
__device__ float g_zg1[GROWS*64];
__device__ float g_zg2[GROWS*256];
__device__ float g_zg3[GROWS*512];
__device__ float g_mug1[64],  g_varg1[64];
__device__ float g_mug2[256], g_varg2[256];
__device__ float g_mug3[512], g_varg3[512];

// ---------------- fast exp2 (MUFU.EX2) ----------------
__device__ __forceinline__ float ex2(float x) {
    float r;
    asm("ex2.approx.f32 %0, %1;" : "=f"(r) : "f"(x));
    return r;
}

// ---------------- bf16 double-double helpers ----------------
__device__ __forceinline__ unsigned bfpack(float lo, float hi) {
    unsigned r;
    asm("cvt.rn.bf16x2.f32 %0, %1, %2;" : "=r"(r) : "f"(hi), "f"(lo));
    return r;
}
__device__ __forceinline__ uint2 bfsplit2(float x0, float x1) {
    unsigned hp = bfpack(x0, x1);
    float h0 = __uint_as_float(hp << 16);
    float h1 = __uint_as_float(hp & 0xffff0000u);
    unsigned lp = bfpack(x0 - h0, x1 - h1);
    return make_uint2(hp, lp);
}
__device__ __forceinline__ void mmabf(float* d,
                                      unsigned a0, unsigned a1, unsigned a2, unsigned a3,
                                      unsigned b0, unsigned b1) {
    asm volatile("mma.sync.aligned.m16n8k16.row.col.f32.bf16.bf16.f32 "
        "{%0,%1,%2,%3}, {%4,%5,%6,%7}, {%8,%9}, {%0,%1,%2,%3};"
        : "+f"(d[0]), "+f"(d[1]), "+f"(d[2]), "+f"(d[3])
        : "r"(a0), "r"(a1), "r"(a2), "r"(a3), "r"(b0), "r"(b1));
}
__device__ __forceinline__ void mma3(float* d, const uint2* a, uint2 b0, uint2 b1) {
    mmabf(d, a[0].x, a[1].x, a[2].x, a[3].x, b0.x, b1.x);
    mmabf(d, a[0].x, a[1].x, a[2].x, a[3].x, b0.y, b1.y);
    mmabf(d, a[0].y, a[1].y, a[2].y, a[3].y, b0.x, b1.x);
}

// ---------------- tf32 helpers (k_gemm_bt) ----------------
__device__ __forceinline__ uint2 tf32x2(float x) {
    unsigned hi, lo;
    asm("cvt.rna.tf32.f32 %0, %1;" : "=r"(hi) : "f"(x));
    float r = x - __uint_as_float(hi);
    asm("cvt.rna.tf32.f32 %0, %1;" : "=r"(lo) : "f"(r));
    return make_uint2(hi, lo);
}
__device__ __forceinline__ void mma8(float* d,
                                     unsigned a0, unsigned a1, unsigned a2, unsigned a3,
                                     unsigned b0, unsigned b1) {
    asm volatile("mma.sync.aligned.m16n8k8.row.col.f32.tf32.tf32.f32 "
        "{%0,%1,%2,%3}, {%4,%5,%6,%7}, {%8,%9}, {%0,%1,%2,%3};"
        : "+f"(d[0]), "+f"(d[1]), "+f"(d[2]), "+f"(d[3])
        : "r"(a0), "r"(a1), "r"(a2), "r"(a3), "r"(b0), "r"(b1));
}
__device__ __forceinline__ void mma_x3t(float* d, const uint2* a, uint2 b0, uint2 b1) {
    mma8(d, a[0].x, a[1].x, a[2].x, a[3].x, b0.x, b1.x);
    mma8(d, a[0].x, a[1].x, a[2].x, a[3].x, b0.y, b1.y);
    mma8(d, a[0].y, a[1].y, a[2].y, a[3].y, b0.x, b1.x);
}

// ---------------- (B,C,N) -> (B,N,C) ----------------
__global__ __launch_bounds__(256) void k_transpose(const float* __restrict__ src,
                                                   float* __restrict__ dst) {
    __shared__ float t[32][33];
    int b = blockIdx.z, n0 = blockIdx.x*32, c0 = blockIdx.y*32;
    int tx = threadIdx.x, ty = threadIdx.y;
    #pragma unroll
    for (int i = 0; i < 32; i += 8)
        t[ty+i][tx] = src[((size_t)b*CC + c0 + ty + i)*NN + n0 + tx];
    __syncthreads();
    #pragma unroll
    for (int i = 0; i < 32; i += 8)
        dst[((size_t)b*NN + n0 + ty + i)*CC + c0 + tx] = t[tx][ty+i];
}

// ---------------- bf16x3 GEMM (R7 version), 3 B/C via blockIdx.z ------------
#define AS_RS 20
#define BT_RS 20
__global__ __launch_bounds__(256) void k_gemm3(const float* __restrict__ A,
                                               const float* __restrict__ B0,
                                               const float* __restrict__ B1,
                                               const float* __restrict__ B2,
                                               float* __restrict__ C0,
                                               float* __restrict__ C1,
                                               float* __restrict__ C2,
                                               int Kd, int Nc) {
    __shared__ uint2 As[128*AS_RS];
    __shared__ uint2 Bt[64*BT_RS];
    const float* B = (blockIdx.z == 0) ? B0 : (blockIdx.z == 1 ? B1 : B2);
    float*       C = (blockIdx.z == 0) ? C0 : (blockIdx.z == 1 ? C1 : C2);
    int tid = threadIdx.x;
    int w = tid >> 5, lane = tid & 31, g = lane >> 2, tg = lane & 3;
    int mt = w >> 1, nh = w & 1;
    int bm = blockIdx.x*128, bn = blockIdx.y*64;
    float acc[2][4][4];
    #pragma unroll
    for (int m = 0; m < 2; m++)
        #pragma unroll
        for (int nt = 0; nt < 4; nt++)
            #pragma unroll
            for (int i = 0; i < 4; i++) acc[m][nt][i] = 0.f;

    int bkp = tid & 15, bng = tid >> 4;
    for (int k0 = 0; k0 < Kd; k0 += 32) {
        #pragma unroll
        for (int it = 0; it < 4; it++) {
            int i = tid + it*256;
            int r = i >> 3, c = (i & 7) << 2;
            float4 v = *(const float4*)(A + (size_t)(bm+r)*Kd + k0 + c);
            uint2 p0 = bfsplit2(v.x, v.y), p1 = bfsplit2(v.z, v.w);
            *(uint4*)&As[r*AS_RS + (c >> 1)] = make_uint4(p0.x, p0.y, p1.x, p1.y);
        }
        {
            const float* bp0 = B + (size_t)(k0 + 2*bkp)*Nc + bn + 4*bng;
            float4 x = *(const float4*)bp0;
            float4 y = *(const float4*)(bp0 + Nc);
            Bt[(4*bng+0)*BT_RS + bkp] = bfsplit2(x.x, y.x);
            Bt[(4*bng+1)*BT_RS + bkp] = bfsplit2(x.y, y.y);
            Bt[(4*bng+2)*BT_RS + bkp] = bfsplit2(x.z, y.z);
            Bt[(4*bng+3)*BT_RS + bkp] = bfsplit2(x.w, y.w);
        }
        __syncthreads();
        #pragma unroll
        for (int kk = 0; kk < 2; kk++) {
            int kb = kk*8;
            uint2 af[2][4];
            #pragma unroll
            for (int m = 0; m < 2; m++) {
                int r0 = mt*32 + m*16 + g;
                af[m][0] = As[r0*AS_RS + kb+tg];
                af[m][1] = As[(r0+8)*AS_RS + kb+tg];
                af[m][2] = As[r0*AS_RS + kb+tg+4];
                af[m][3] = As[(r0+8)*AS_RS + kb+tg+4];
            }
            #pragma unroll
            for (int nt = 0; nt < 4; nt++) {
                int n0 = nh*32 + nt*8;
                uint2 b0 = Bt[(n0+g)*BT_RS + kb+tg];
                uint2 b1 = Bt[(n0+g)*BT_RS + kb+tg+4];
                mma3(acc[0][nt], af[0], b0, b1);
                mma3(acc[1][nt], af[1], b0, b1);
            }
        }
        __syncthreads();
    }
    #pragma unroll
    for (int m = 0; m < 2; m++)
        #pragma unroll
        for (int nt = 0; nt < 4; nt++) {
            int row = bm + mt*32 + m*16 + g;
            int col = bn + nh*32 + nt*8 + 2*tg;
            *(float2*)(C + (size_t)row*Nc + col) = make_float2(acc[m][nt][0], acc[m][nt][1]);
            *(float2*)(C + (size_t)(row+8)*Nc + col) = make_float2(acc[m][nt][2], acc[m][nt][3]);
        }
}

// ------- tf32x3 GEMM, B transposed (W[N x K] row-major), optional BN+act ----
__global__ __launch_bounds__(256) void k_gemm_bt(const float* __restrict__ A,
                                                 const float* __restrict__ W,
                                                 const float* __restrict__ bias,
                                                 const float* __restrict__ mu,
                                                 const float* __restrict__ var,
                                                 const float* __restrict__ gam,
                                                 const float* __restrict__ bet,
                                                 int act,
                                                 float* __restrict__ C,
                                                 int M, int Kd, int Nc) {
    __shared__ float As[128][36];
    __shared__ float Ws[64][36];
    int tid = threadIdx.x;
    int w = tid >> 5, lane = tid & 31, g = lane >> 2, tg = lane & 3;
    int mt = w >> 1, nh = w & 1;
    int bm = blockIdx.x*128, bn = blockIdx.y*64;
    float acc[2][4][4];
    #pragma unroll
    for (int m = 0; m < 2; m++)
        #pragma unroll
        for (int nt = 0; nt < 4; nt++)
            #pragma unroll
            for (int i = 0; i < 4; i++) acc[m][nt][i] = 0.f;

    for (int k0 = 0; k0 < Kd; k0 += 32) {
        #pragma unroll
        for (int it = 0; it < 4; it++) {
            int i = tid + it*256;
            int r = i >> 3, c = (i & 7) << 2;
            int gr = bm + r;
            float4 v = (gr < M) ? *(const float4*)(A + (size_t)gr*Kd + k0 + c)
                                : make_float4(0.f,0.f,0.f,0.f);
            if (act == 2) {
                float* vv = (float*)&v;
                #pragma unroll
                for (int j = 0; j < 4; j++) {
                    int cc = k0 + c + j;
                    float sc = gam[cc]*rsqrtf(var[cc]+EPSV);
                    float t = (vv[j] - mu[cc])*sc + bet[cc];
                    vv[j] = (t > 0.f) ? t : 0.2f*t;
                }
            }
            *(float4*)&As[r][c] = v;
        }
        #pragma unroll
        for (int it = 0; it < 2; it++) {
            int i = tid + it*256;
            int r = i >> 3, c = (i & 7) << 2;
            *(float4*)&Ws[r][c] = *(const float4*)(W + (size_t)(bn+r)*Kd + k0 + c);
        }
        __syncthreads();
        #pragma unroll
        for (int kk = 0; kk < 4; kk++) {
            int kb = kk*8;
            uint2 af[2][4];
            #pragma unroll
            for (int m = 0; m < 2; m++) {
                int r0 = mt*32 + m*16 + g;
                af[m][0] = tf32x2(As[r0  ][kb+tg]);
                af[m][1] = tf32x2(As[r0+8][kb+tg]);
                af[m][2] = tf32x2(As[r0  ][kb+tg+4]);
                af[m][3] = tf32x2(As[r0+8][kb+tg+4]);
            }
            #pragma unroll
            for (int nt = 0; nt < 4; nt++) {
                int n0 = nh*32 + nt*8;
                uint2 b0 = tf32x2(Ws[n0+g][kb+tg]);
                uint2 b1 = tf32x2(Ws[n0+g][kb+tg+4]);
                mma_x3t(acc[0][nt], af[0], b0, b1);
                mma_x3t(acc[1][nt], af[1], b0, b1);
            }
        }
        __syncthreads();
    }
    #pragma unroll
    for (int m = 0; m < 2; m++)
        #pragma unroll
        for (int nt = 0; nt < 4; nt++) {
            int row = bm + mt*32 + m*16 + g;
            int col = bn + nh*32 + nt*8 + 2*tg;
            float b0v = bias ? bias[col]   : 0.f;
            float b1v = bias ? bias[col+1] : 0.f;
            if (row < M)
                *(float2*)(C + (size_t)row*Nc + col) =
                    make_float2(acc[m][nt][0]+b0v, acc[m][nt][1]+b1v);
            if (row + 8 < M)
                *(float2*)(C + (size_t)(row+8)*Nc + col) =
                    make_float2(acc[m][nt][2]+b0v, acc[m][nt][3]+b1v);
        }
}

// -------- flash: 128-key staging rounds, MUFU exp2, register softmax -------
#define KS_RS 20           // uint2 stride, Ks[128 keys][16 dh-pairs]
#define VT_RS 68           // uint2 stride, Vt[32 dh][64 key-pairs]
__global__ __launch_bounds__(256) void k_flash(const float* __restrict__ Q,
                                               const float* __restrict__ K,
                                               const float* __restrict__ V,
                                               float* __restrict__ O) {
    __shared__ uint2 Ks[128*KS_RS];
    __shared__ uint2 Vt[32*VT_RS];

    int tid = threadIdx.x;
    int w = tid >> 5, lane = tid & 31, g = lane >> 2, tg = lane & 3;
    int qt = blockIdx.x, h = blockIdx.y, b = blockIdx.z;
    const size_t rowbase = (size_t)b*NN + (size_t)qt*128;
    const float* qb = Q + rowbase*CC + h*32;
    const float* kb = K + (size_t)b*NN*CC + h*32;
    const float* vb = V + (size_t)b*NN*CC + h*32;

    const float qsc = 0.1767766952966369f * 1.4426950408889634f;
    int r0 = w*16 + g;
    uint2 qf[2][4];
    #pragma unroll
    for (int kk = 0; kk < 2; kk++) {
        int cb = kk*16 + 2*tg;
        float2 x0 = *(const float2*)(qb + (size_t)r0*CC + cb);
        float2 x1 = *(const float2*)(qb + (size_t)(r0+8)*CC + cb);
        float2 x2 = *(const float2*)(qb + (size_t)r0*CC + cb + 8);
        float2 x3 = *(const float2*)(qb + (size_t)(r0+8)*CC + cb + 8);
        qf[kk][0] = bfsplit2(x0.x*qsc, x0.y*qsc);
        qf[kk][1] = bfsplit2(x1.x*qsc, x1.y*qsc);
        qf[kk][2] = bfsplit2(x2.x*qsc, x2.y*qsc);
        qf[kk][3] = bfsplit2(x3.x*qsc, x3.y*qsc);
    }

    float of[4][4];
    #pragma unroll
    for (int nt = 0; nt < 4; nt++)
        #pragma unroll
        for (int i = 0; i < 4; i++) of[nt][i] = 0.f;
    float l0 = 0.f, l1 = 0.f;

    int vj = tid & 63, vcq = tid >> 6;   // V: keypair vj, dh cols vcq*8..+7

    for (int c0 = 0; c0 < NN; c0 += 128) {
        __syncthreads();   // prior round's MMA reads done before restage
        #pragma unroll
        for (int it = 0; it < 4; it++) {     // K: 128 keys x 32 dh
            int i = tid + it*256;
            int r = i >> 3, c = (i & 7) << 2;
            float4 kv = *(const float4*)(kb + (size_t)(c0+r)*CC + c);
            uint2 p0 = bfsplit2(kv.x, kv.y), p1 = bfsplit2(kv.z, kv.w);
            *(uint4*)&Ks[r*KS_RS + (c >> 1)] = make_uint4(p0.x, p0.y, p1.x, p1.y);
        }
        {                                    // V transposed: Vt[dh][keypair]
            int c = vcq*8;
            const float* v0 = vb + (size_t)(c0 + 2*vj)*CC + c;
            float4 a4 = *(const float4*)v0;
            float4 a5 = *(const float4*)(v0 + 4);
            float4 b4 = *(const float4*)(v0 + CC);
            float4 b5 = *(const float4*)(v0 + CC + 4);
            Vt[(c+0)*VT_RS + vj] = bfsplit2(a4.x, b4.x);
            Vt[(c+1)*VT_RS + vj] = bfsplit2(a4.y, b4.y);
            Vt[(c+2)*VT_RS + vj] = bfsplit2(a4.z, b4.z);
            Vt[(c+3)*VT_RS + vj] = bfsplit2(a4.w, b4.w);
            Vt[(c+4)*VT_RS + vj] = bfsplit2(a5.x, b5.x);
            Vt[(c+5)*VT_RS + vj] = bfsplit2(a5.y, b5.y);
            Vt[(c+6)*VT_RS + vj] = bfsplit2(a5.z, b5.z);
            Vt[(c+7)*VT_RS + vj] = bfsplit2(a5.w, b5.w);
        }
        __syncthreads();

        #pragma unroll
        for (int hb = 0; hb < 2; hb++) {
            const uint2* Kh = Ks + hb*64*KS_RS;
            int vb0 = hb*32;
            // S (log2 domain) -> MUFU.EX2 -> bf16 pairs in registers
            uint2 Pl[8], Ph[8];
            #pragma unroll
            for (int nt = 0; nt < 8; nt++) {
                float sacc[4] = {0.f, 0.f, 0.f, 0.f};
                int n0 = nt*8;
                #pragma unroll
                for (int kk = 0; kk < 2; kk++) {
                    int kb2 = kk*8;
                    uint2 b0 = Kh[(n0+g)*KS_RS + kb2+tg];
                    uint2 b1 = Kh[(n0+g)*KS_RS + kb2+tg+4];
                    mma3(sacc, qf[kk], b0, b1);
                }
                float e0 = ex2(sacc[0]), e1 = ex2(sacc[1]);
                float e2 = ex2(sacc[2]), e3 = ex2(sacc[3]);
                l0 += e0 + e1;
                l1 += e2 + e3;
                Pl[nt] = bfsplit2(e0, e1);
                Ph[nt] = bfsplit2(e2, e3);
            }
            // O += P @ V
            #pragma unroll
            for (int kk = 0; kk < 4; kk++) {
                uint2 pa[4] = {Pl[2*kk], Ph[2*kk], Pl[2*kk+1], Ph[2*kk+1]};
                int kb2 = kk*8;
                #pragma unroll
                for (int nt = 0; nt < 4; nt++) {
                    int n0 = nt*8;
                    uint2 b0 = Vt[(n0+g)*VT_RS + vb0 + kb2+tg];
                    uint2 b1 = Vt[(n0+g)*VT_RS + vb0 + kb2+tg+4];
                    mma3(of[nt], pa, b0, b1);
                }
            }
        }
    }

    l0 += __shfl_xor_sync(0xffffffffu, l0, 1);
    l0 += __shfl_xor_sync(0xffffffffu, l0, 2);
    l1 += __shfl_xor_sync(0xffffffffu, l1, 1);
    l1 += __shfl_xor_sync(0xffffffffu, l1, 2);
    float inv0 = 1.f / l0, inv1 = 1.f / l1;
    #pragma unroll
    for (int nt = 0; nt < 4; nt++) {
        int c = nt*8 + 2*tg;
        *(float2*)(O + (rowbase + r0)*CC + h*32 + c) =
            make_float2(of[nt][0]*inv0, of[nt][1]*inv0);
        *(float2*)(O + (rowbase + r0 + 8)*CC + h*32 + c) =
            make_float2(of[nt][2]*inv1, of[nt][3]*inv1);
    }
}

__global__ __launch_bounds__(256) void k_lnres(const float* __restrict__ xin,
                                               const float* __restrict__ o,
                                               const float* __restrict__ g,
                                               const float* __restrict__ bta,
                                               float* __restrict__ xout) {
    int row = blockIdx.x*8 + threadIdx.y;
    int lane = threadIdx.x;
    const float* xr = xin + (size_t)row*CC;
    const float* orr = o + (size_t)row*CC;
    float v[8]; float s = 0.f;
    #pragma unroll
    for (int i = 0; i < 8; i++) { int c = lane + i*32; v[i] = xr[c] + orr[c]; s += v[i]; }
    #pragma unroll
    for (int off = 16; off; off >>= 1) s += __shfl_xor_sync(0xffffffffu, s, off);
    float mean = s * (1.f/256.f);
    float vs = 0.f;
    #pragma unroll
    for (int i = 0; i < 8; i++) { float d = v[i]-mean; vs += d*d; }
    #pragma unroll
    for (int off = 16; off; off >>= 1) vs += __shfl_xor_sync(0xffffffffu, vs, off);
    float rstd = rsqrtf(vs*(1.f/256.f) + EPSV);
    #pragma unroll
    for (int i = 0; i < 8; i++) {
        int c = lane + i*32;
        xout[(size_t)row*CC + c] = (v[i]-mean)*rstd*g[c] + bta[c];
    }
}

__global__ __launch_bounds__(256) void k_stats(const float* __restrict__ z, int rows, int C,
                                               float* __restrict__ mu, float* __restrict__ var) {
    int lane = threadIdx.x & 31;
    int rl = threadIdx.x >> 5;
    int c = blockIdx.x*32 + lane;
    float s = 0.f, sq = 0.f;
    if (c < C)
        for (int r = rl; r < rows; r += 8) {
            float v = z[(size_t)r*C + c]; s += v; sq += v*v;
        }
    __shared__ float ss[8][33], qq[8][33];
    ss[rl][lane] = s; qq[rl][lane] = sq;
    __syncthreads();
    if (rl == 0 && c < C) {
        float S = 0.f, Qq = 0.f;
        #pragma unroll
        for (int j = 0; j < 8; j++) { S += ss[j][lane]; Qq += qq[j][lane]; }
        float m = S / rows;
        mu[c] = m; var[c] = fmaxf(Qq / rows - m*m, 0.f);
    }
}

__global__ __launch_bounds__(256) void k_dense(const float* __restrict__ in, int Cin,
                                               const float* __restrict__ w,
                                               const float* __restrict__ bias,
                                               const float* __restrict__ mu,
                                               const float* __restrict__ var,
                                               const float* __restrict__ gam,
                                               const float* __restrict__ bet,
                                               int act,
                                               float* __restrict__ out, int Cout) {
    __shared__ float a_s[32*64];
    int rowbase = blockIdx.x*32;
    int tid = threadIdx.x;
    for (int i = tid; i < 32*Cin; i += 256) {
        int r = i / Cin, c = i - r*Cin;
        float v = in[(size_t)(rowbase+r)*Cin + c];
        if (act) {
            float sc = gam[c]*rsqrtf(var[c]+EPSV);
            v = (v - mu[c])*sc + bet[c];
            v = (act == 1) ? fmaxf(v, 0.f) : (v > 0.f ? v : 0.2f*v);
        }
        a_s[i] = v;
    }
    __syncthreads();
    int npairs = Cout*4;
    for (int pr = tid; pr < npairs; pr += 256) {
        int o = pr % Cout, rb = (pr / Cout)*8;
        float bz = bias ? bias[o] : 0.f;
        float acc[8];
        #pragma unroll
        for (int r = 0; r < 8; r++) acc[r] = bz;
        const float* wr = w + (size_t)o*Cin;
        for (int c = 0; c < Cin; c += 4) {
            float4 wv = *(const float4*)(wr + c);
            #pragma unroll
            for (int r = 0; r < 8; r++) {
                float4 av = *(const float4*)(a_s + (rb+r)*Cin + c);
                acc[r] += wv.x*av.x + wv.y*av.y + wv.z*av.z + wv.w*av.w;
            }
        }
        #pragma unroll
        for (int r = 0; r < 8; r++)
            out[(size_t)(rowbase+rb+r)*Cout + o] = acc[r];
    }
}

__global__ __launch_bounds__(256) void k_argmax(const float* __restrict__ z3,
                                                const float* __restrict__ mu,
                                                const float* __restrict__ var,
                                                const float* __restrict__ gam,
                                                const float* __restrict__ bet,
                                                int* __restrict__ idx) {
    int bc = blockIdx.x;
    int b = bc >> 4, c = bc & 15;
    int tid = threadIdx.x;
    float sc = gam[c]*rsqrtf(var[c]+EPSV);
    float sh = bet[c] - mu[c]*sc;
    float best = -1.f; int bi = 1 << 30;
    for (int n = tid; n < NN; n += 256) {
        float v = fmaxf(z3[(size_t)(b*NN+n)*16 + c]*sc + sh, 0.f);
        if (v > best) { best = v; bi = n; }
    }
    __shared__ float bv[256]; __shared__ int bx[256];
    bv[tid] = best; bx[tid] = bi;
    __syncthreads();
    for (int off = 128; off; off >>= 1) {
        if (tid < off) {
            if (bv[tid+off] > bv[tid] || (bv[tid+off] == bv[tid] && bx[tid+off] < bx[tid])) {
                bv[tid] = bv[tid+off]; bx[tid] = bx[tid+off];
            }
        }
        __syncthreads();
    }
    if (tid == 0) idx[bc] = bx[0];
}

__global__ void k_ballq(const float* __restrict__ pts, const int* __restrict__ idx,
                        float* __restrict__ grouped) {
    int e = blockIdx.x;
    int b = e >> 4;
    int lane = threadIdx.x;
    const float* px = pts + (size_t)b*3*NN;
    int qi = idx[e];
    float qx = px[qi], qy = px[NN+qi], qz = px[2*NN+qi];
    float qq = qx*qx + qy*qy + qz*qz;
    __shared__ int gi[32];
    int cnt = 0;
    for (int base = 0; base < NN && cnt < 32; base += 32) {
        int n = base + lane;
        float x = px[n], y = px[NN+n], z = px[2*NN+n];
        float pp = x*x + y*y + z*z;
        float d = qq + pp - 2.f*(qx*x + qy*y + qz*z);
        bool in = !(d > RAD2);
        unsigned m = __ballot_sync(0xffffffffu, in);
        int pos = cnt + __popc(m & ((1u << lane) - 1u));
        if (in && pos < 32) gi[pos] = n;
        cnt += __popc(m);
    }
    __syncwarp();
    if (cnt > 32) cnt = 32;
    int g0 = gi[0];
    int g = (lane < cnt) ? gi[lane] : g0;
    if (lane == 0) {
        grouped[(size_t)e*KG*3+0] = qx;
        grouped[(size_t)e*KG*3+1] = qy;
        grouped[(size_t)e*KG*3+2] = qz;
    }
    size_t o = ((size_t)e*KG + 1 + lane)*3;
    grouped[o+0] = px[g]; grouped[o+1] = px[NN+g]; grouped[o+2] = px[2*NN+g];
}

__global__ __launch_bounds__(256) void k_gc1(const float* __restrict__ grouped,
                                             const float* __restrict__ w,
                                             float* __restrict__ out) {
    int i = blockIdx.x*256 + threadIdx.x;
    if (i >= GROWS*64) return;
    int o = i & 63, r = i >> 6;
    const float* p = grouped + (size_t)r*3;
    const float* wr = w + o*3;
    out[i] = wr[0]*p[0] + wr[1]*p[1] + wr[2]*p[2];
}

__global__ __launch_bounds__(256) void k_finalmax(const float* __restrict__ zg3,
                                                  const float* __restrict__ mu,
                                                  const float* __restrict__ var,
                                                  const float* __restrict__ gam,
                                                  const float* __restrict__ bet,
                                                  float* __restrict__ out) {
    int i = blockIdx.x*256 + threadIdx.x;
    if (i >= EG*512) return;
    int c = i & 511, e = i >> 9;
    int b = e >> 4, s = e & 15;
    float sc = gam[c]*rsqrtf(var[c]+EPSV);
    float sh = bet[c] - mu[c]*sc;
    float mx = -3.0e30f;
    const float* base = zg3 + (size_t)e*KG*512 + c;
    #pragma unroll 1
    for (int k = 0; k < KG; k++) {
        float v = base[(size_t)k*512]*sc + sh;
        v = (v > 0.f) ? v : 0.2f*v;
        mx = fmaxf(mx, v);
    }
    out[((size_t)b*512 + c)*16 + s] = mx;
}

extern "C" void kernel_launch(void* const* d_in, const int* in_sizes, int n_in,
                              void* d_out, int out_size) {
    const float* hoch = (const float*)d_in[0];
    const float* pts  = (const float*)d_in[1];
    const float* Wq   = (const float*)d_in[2];
    const float* Wk   = (const float*)d_in[3];
    const float* Wv   = (const float*)d_in[4];
    const float* Wo   = (const float*)d_in[5];
    const float* ln_g = (const float*)d_in[6];
    const float* ln_b = (const float*)d_in[7];
    const float* fgw1 = (const float*)d_in[8];
    const float* fgb1 = (const float*)d_in[9];
    const float* fgw2 = (const float*)d_in[10];
    const float* fgb2 = (const float*)d_in[11];
    const float* fgw3 = (const float*)d_in[12];
    const float* fgb3 = (const float*)d_in[13];
    const float* fgg1 = (const float*)d_in[14];
    const float* fge1 = (const float*)d_in[15];
    const float* fgg2 = (const float*)d_in[16];
    const float* fge2 = (const float*)d_in[17];
    const float* fgg3 = (const float*)d_in[18];
    const float* fge3 = (const float*)d_in[19];
    const float* cw1  = (const float*)d_in[20];
    const float* cw2  = (const float*)d_in[21];
    const float* cw3  = (const float*)d_in[22];
    const float* cg1  = (const float*)d_in[23];
    const float* cb1  = (const float*)d_in[24];
    const float* cg2  = (const float*)d_in[25];
    const float* cb2  = (const float*)d_in[26];
    const float* cg3  = (const float*)d_in[27];
    const float* cb3  = (const float*)d_in[28];
    float* out = (float*)d_out;

    void* a;
    cudaGetSymbolAddress(&a, g_x);       float* x   = (float*)a;
    cudaGetSymbolAddress(&a, g_q);       float* q   = (float*)a;
    cudaGetSymbolAddress(&a, g_k);       float* k   = (float*)a;
    cudaGetSymbolAddress(&a, g_v);       float* v   = (float*)a;
    cudaGetSymbolAddress(&a, g_ao);      float* ao  = (float*)a;
    cudaGetSymbolAddress(&a, g_pr);      float* pr  = (float*)a;
    cudaGetSymbolAddress(&a, g_z1);      float* z1  = (float*)a;
    cudaGetSymbolAddress(&a, g_z2);      float* z2  = (float*)a;
    cudaGetSymbolAddress(&a, g_z3);      float* z3  = (float*)a;
    cudaGetSymbolAddress(&a, g_mu1);     float* mu1 = (float*)a;
    cudaGetSymbolAddress(&a, g_var1);    float* va1 = (float*)a;
    cudaGetSymbolAddress(&a, g_mu2);     float* mu2 = (float*)a;
    cudaGetSymbolAddress(&a, g_var2);    float* va2 = (float*)a;
    cudaGetSymbolAddress(&a, g_mu3);     float* mu3 = (float*)a;
    cudaGetSymbolAddress(&a, g_var3);    float* va3 = (float*)a;
    cudaGetSymbolAddress(&a, g_idx);     int*   idx = (int*)a;
    cudaGetSymbolAddress(&a, g_grouped); float* grp = (float*)a;
    cudaGetSymbolAddress(&a, g_zg1);     float* zg1 = (float*)a;
    cudaGetSymbolAddress(&a, g_zg2);     float* zg2 = (float*)a;
    cudaGetSymbolAddress(&a, g_zg3);     float* zg3 = (float*)a;
    cudaGetSymbolAddress(&a, g_mug1);    float* mg1 = (float*)a;
    cudaGetSymbolAddress(&a, g_varg1);   float* vg1 = (float*)a;
    cudaGetSymbolAddress(&a, g_mug2);    float* mg2 = (float*)a;
    cudaGetSymbolAddress(&a, g_varg2);   float* vg2 = (float*)a;
    cudaGetSymbolAddress(&a, g_mug3);    float* mg3 = (float*)a;
    cudaGetSymbolAddress(&a, g_varg3);   float* vg3 = (float*)a;

    k_transpose<<<dim3(NN/32, CC/32, BB), dim3(32,8)>>>(hoch, x);

    for (int l = 0; l < LL; l++) {
        const float* wq = Wq + (size_t)l*CC*CC;
        const float* wk = Wk + (size_t)l*CC*CC;
        const float* wv = Wv + (size_t)l*CC*CC;
        const float* wo = Wo + (size_t)l*CC*CC;
        k_gemm3<<<dim3(NROWS/128, CC/64, 3), 256>>>(x, wq, wk, wv, q, k, v, CC, CC);
        k_flash<<<dim3(NN/128, HH, BB), 256>>>(q, k, v, ao);
        k_gemm3<<<dim3(NROWS/128, CC/64, 1), 256>>>(ao, wo, wo, wo, pr, pr, pr, CC, CC);
        k_lnres<<<NROWS/8, dim3(32,8)>>>(x, pr, ln_g + l*CC, ln_b + l*CC, x);
    }

    k_gemm_bt<<<dim3(NROWS/128, 1), 256>>>(x, fgw1, fgb1, 0, 0, 0, 0, 0, z1, NROWS, 256, 64);
    k_stats<<<2, 256>>>(z1, NROWS, 64, mu1, va1);
    k_dense<<<NROWS/32, 256>>>(z1, 64, fgw2, fgb2, mu1, va1, fgg1, fge1, 1, z2, 32);
    k_stats<<<1, 256>>>(z2, NROWS, 32, mu2, va2);
    k_dense<<<NROWS/32, 256>>>(z2, 32, fgw3, fgb3, mu2, va2, fgg2, fge2, 1, z3, 16);
    k_stats<<<1, 256>>>(z3, NROWS, 16, mu3, va3);
    k_argmax<<<EG, 256>>>(z3, mu3, va3, fgg3, fge3, idx);

    k_ballq<<<EG, 32>>>(pts, idx, grp);
    k_gc1<<<(GROWS*64 + 255)/256, 256>>>(grp, cw1, zg1);
    k_stats<<<2, 256>>>(zg1, GROWS, 64, mg1, vg1);
    k_dense<<<GROWS/32, 256>>>(zg1, 64, cw2, 0, mg1, vg1, cg1, cb1, 2, zg2, 256);
    k_stats<<<8, 256>>>(zg2, GROWS, 256, mg2, vg2);
    k_gemm_bt<<<dim3((GROWS+127)/128, 8), 256>>>(zg2, cw3, 0, mg2, vg2, cg2, cb2, 2, zg3, GROWS, 256, 512);
    k_stats<<<16, 256>>>(zg3, GROWS, 512, mg3, vg3);
    k_finalmax<<<(EG*512 + 255)/256, 256>>>(zg3, mg3, vg3, cg3, cb3, out);
}